// round 11
// baseline (speedup 1.0000x reference)
#include <cuda_runtime.h>
#include <math.h>

#define NF   128   // num_filters
#define NG   50    // num_gauss
#define HID  128   // hidden
#define TE   64    // edges per tile
#define RP   68    // padded transposed-tile row length (16B-aligned rows)
#define MAXN 50000
#define MAXE 800000

typedef unsigned long long u64;

// Scratch (no allocation allowed)
__device__ float g_h[MAXN * NF];     // h = x @ lin1^T
__device__ float g_agg[MAXN * NF];   // segment_sum result
__device__ float g_tmp[MAXN * HID];  // ssp(agg @ lin2^T + b)
__device__ float g_w1T[NG * NF];     // w1 transposed [k][f]
__device__ int   g_idx[2 * MAXE];    // normalized int32 edge indices [src | dst]
__device__ int   g_is64;             // dtype flag for edge_index

__device__ __forceinline__ float ssp(float v) {
    return fmaxf(v, 0.0f) + log1pf(expf(-fabsf(v))) - 0.69314718055994531f;
}

// ---- packed fp32x2 helpers (Blackwell FFMA2) --------------------------------
__device__ __forceinline__ u64 splat2(float a) {
    u64 r; asm("mov.b64 %0, {%1, %1};" : "=l"(r) : "f"(a)); return r;
}
__device__ __forceinline__ void fma2(u64& d, u64 a, u64 b) {
    asm("fma.rn.f32x2 %0, %1, %2, %0;" : "+l"(d) : "l"(a), "l"(b));
}
__device__ __forceinline__ float2 unpack2(u64 v) {
    float2 f; asm("mov.b64 {%0, %1}, %2;" : "=f"(f.x), "=f"(f.y) : "l"(v)); return f;
}

// Swizzled index (node_gemm only)
__device__ __forceinline__ int widx(int k, int fg) {
    return k * NF + (((fg) ^ (k & 31)) << 2);
}

// ---------------------------------------------------------------------------
// prep kernels (unchanged, proven)
// ---------------------------------------------------------------------------
__global__ void detect_idx_kernel(const unsigned int* __restrict__ w, int nwords) {
    __shared__ int nonzero;
    if (threadIdx.x == 0) nonzero = 0;
    __syncthreads();
    int idx = 1 + 2 * (int)threadIdx.x;
    if (idx < nwords && w[idx] != 0u) atomicExch(&nonzero, 1);
    __syncthreads();
    if (threadIdx.x == 0) g_is64 = (nonzero == 0) ? 1 : 0;
}

__global__ void convert_idx_kernel(const void* __restrict__ ei, int n2e) {
    int i = blockIdx.x * blockDim.x + threadIdx.x;
    if (i < n2e)
        g_idx[i] = g_is64 ? (int)((const long long*)ei)[i] : ((const int*)ei)[i];
}

__global__ void transpose_w1_kernel(const float* __restrict__ w1) {
    int i = blockIdx.x * blockDim.x + threadIdx.x;
    if (i < NF * NG) {
        int f = i / NG, k = i - f * NG;
        g_w1T[k * NF + f] = w1[i];
    }
}

__global__ void zero_kernel(float4* __restrict__ p, int n4) {
    int i = blockIdx.x * blockDim.x + threadIdx.x;
    if (i < n4) p[i] = make_float4(0.f, 0.f, 0.f, 0.f);
}

// ---------------------------------------------------------------------------
// Node GEMM (unchanged from working R9)
// ---------------------------------------------------------------------------
template <bool SSP, bool HASB>
__global__ void __launch_bounds__(256)
node_gemm(const float* __restrict__ A, const float* __restrict__ W,
          const float* __restrict__ bias, float* __restrict__ out, int N)
{
    extern __shared__ float sm[];
    float* wT = sm;
    float* aN = sm + NF * NF;

    const int tid = threadIdx.x;
    const int rbase = blockIdx.x * TE;

    for (int i = tid; i < NF * NF; i += 256) {
        int f = i >> 7, k = i & (NF - 1);
        wT[widx(k, f >> 2) + (f & 3)] = W[i];
    }
    {
        const float4 z4 = make_float4(0.f, 0.f, 0.f, 0.f);
        for (int i = tid; i < TE * (NF / 4); i += 256) {
            int r = i >> 5;
            int gr = rbase + r;
            ((float4*)aN)[i] = (gr < N)
                ? ((const float4*)A)[(size_t)gr * (NF / 4) + (i & 31)] : z4;
        }
    }
    __syncthreads();

    const int fg = tid & 31, f0 = fg << 2;
    const int r0 = (tid >> 5) << 3;

    u64 acc[8][2];
#pragma unroll
    for (int i = 0; i < 8; i++) { acc[i][0] = 0ULL; acc[i][1] = 0ULL; }

#pragma unroll 8
    for (int k = 0; k < NF; k++) {
        const ulonglong2 wv = *(const ulonglong2*)&wT[widx(k, fg)];
#pragma unroll
        for (int i = 0; i < 8; i++) {
            u64 aa = splat2(aN[(r0 + i) * NF + k]);
            fma2(acc[i][0], aa, wv.x);
            fma2(acc[i][1], aa, wv.y);
        }
    }

    float4 bv = make_float4(0.f, 0.f, 0.f, 0.f);
    if (HASB) bv = *(const float4*)(bias + f0);

#pragma unroll
    for (int i = 0; i < 8; i++) {
        int gr = rbase + r0 + i;
        if (gr < N) {
            float2 p0 = unpack2(acc[i][0]);
            float2 p1 = unpack2(acc[i][1]);
            float4 v;
            v.x = p0.x + bv.x;
            v.y = p0.y + bv.y;
            v.z = p1.x + bv.z;
            v.w = p1.y + bv.w;
            if (SSP) { v.x = ssp(v.x); v.y = ssp(v.y); v.z = ssp(v.z); v.w = ssp(v.w); }
            *(float4*)(out + (size_t)gr * NF + f0) = v;
        }
    }
}

// ---------------------------------------------------------------------------
// Fused edge kernel, edge-pair-packed FFMA2 (low LDS-wavefront version).
// Tiles transposed [k][e] (RP-padded): A-operands are broadcast LDS.128
// delivering pre-packed edge pairs; weights splatted once per k (shared by
// all 8 edges). FIX vs R10: epilogue hs[] indexed 2p/2p+1 (local 0..7),
// not the tile-local edge index.
// ---------------------------------------------------------------------------
#define EDGE_SMEM_BYTES ((NF*NF + NG*RP + NF*RP + TE) * 4 + 2 * TE * 4)

__global__ void __launch_bounds__(256, 2)
edge_kernel(const float* __restrict__ ea, const float* __restrict__ ew,
            const float* __restrict__ b1,
            const float* __restrict__ w2, const float* __restrict__ b2,
            const float* __restrict__ h, float* __restrict__ agg, int E)
{
    extern __shared__ float sm[];
    float* w2T  = sm;                    // NF*NF  [k][f] plain
    float* eaT  = w2T + NF * NF;         // NG x RP  ([k][e])
    float* hT   = eaT + NG * RP;         // NF x RP  (layer1 out, [k][e])
    float* sC   = hT  + NF * RP;         // TE
    int*   sSrc = (int*)(sC + TE);       // TE
    int*   sDst = sSrc + TE;             // TE

    const int tid = threadIdx.x;

    // --- w2 to smem once per (persistent) block: [k][f] ---
    for (int i = tid; i < NF * NF; i += 256) {
        int f = i >> 7, k = i & (NF - 1);
        w2T[k * NF + f] = w2[i];
    }

    const int fg = tid & 31, f0 = fg << 2;
    const int e0 = (tid >> 5) << 3;      // 8 edges per warp (4 packed pairs)
    const float4 b1v = *(const float4*)(b1 + f0);
    const float4 b2v = *(const float4*)(b2 + f0);

    const int ntiles = (E + TE - 1) / TE;
    for (int tile = blockIdx.x; tile < ntiles; tile += gridDim.x) {
        const int ebase = tile * TE;
        __syncthreads();   // protect smem tiles across iterations

        // --- stage edge_attr transposed: eaT[k][e] ---
        for (int i = tid; i < TE * NG; i += 256) {
            int e = i / NG, k = i - e * NG;
            int ge = ebase + e;
            eaT[k * RP + e] = (ge < E) ? ea[(size_t)ge * NG + k] : 0.f;
        }
        if (tid < TE) {
            int ge = ebase + tid;
            if (ge < E) {
                sC[tid]   = 0.5f * (cospif(ew[ge] * 0.1f) + 1.0f);
                sSrc[tid] = g_idx[ge];
                sDst[tid] = g_idx[E + ge];
            } else {
                sC[tid] = 0.f; sSrc[tid] = 0; sDst[tid] = 0;
            }
        }
        __syncthreads();

        // --- prefetch h[src] gathers (L2-resident), local index 0..7 ---
        float4 hs[8];
#pragma unroll
        for (int i = 0; i < 8; i++)
            hs[i] = *(const float4*)(h + (size_t)sSrc[e0 + i] * NF + f0);

        // --- layer 1: acc[pair][filter]; w1 via __ldg (L1-resident) ---
        u64 acc[4][4];
#pragma unroll
        for (int p = 0; p < 4; p++)
#pragma unroll
            for (int j = 0; j < 4; j++) acc[p][j] = 0ULL;

#pragma unroll 2
        for (int k = 0; k < NG; k++) {
            const float4 w4 = __ldg((const float4*)&g_w1T[k * NF + f0]);
            u64 ws0 = splat2(w4.x), ws1 = splat2(w4.y);
            u64 ws2 = splat2(w4.z), ws3 = splat2(w4.w);
            const ulonglong2 a01 = *(const ulonglong2*)&eaT[k * RP + e0];     // broadcast
            const ulonglong2 a23 = *(const ulonglong2*)&eaT[k * RP + e0 + 4]; // broadcast
            u64 ap0 = a01.x, ap1 = a01.y, ap2 = a23.x, ap3 = a23.y;
            fma2(acc[0][0], ap0, ws0); fma2(acc[0][1], ap0, ws1);
            fma2(acc[0][2], ap0, ws2); fma2(acc[0][3], ap0, ws3);
            fma2(acc[1][0], ap1, ws0); fma2(acc[1][1], ap1, ws1);
            fma2(acc[1][2], ap1, ws2); fma2(acc[1][3], ap1, ws3);
            fma2(acc[2][0], ap2, ws0); fma2(acc[2][1], ap2, ws1);
            fma2(acc[2][2], ap2, ws2); fma2(acc[2][3], ap2, ws3);
            fma2(acc[3][0], ap3, ws0); fma2(acc[3][1], ap3, ws1);
            fma2(acc[3][2], ap3, ws2); fma2(acc[3][3], ap3, ws3);
        }

        // ssp + store transposed hT[f][e]: per filter j, 8 edge values
#pragma unroll
        for (int j = 0; j < 4; j++) {
            float bj = (j == 0) ? b1v.x : (j == 1) ? b1v.y : (j == 2) ? b1v.z : b1v.w;
            float2 t0 = unpack2(acc[0][j]);
            float2 t1 = unpack2(acc[1][j]);
            float2 t2 = unpack2(acc[2][j]);
            float2 t3 = unpack2(acc[3][j]);
            float4 v0 = make_float4(ssp(t0.x + bj), ssp(t0.y + bj),
                                    ssp(t1.x + bj), ssp(t1.y + bj));
            float4 v1 = make_float4(ssp(t2.x + bj), ssp(t2.y + bj),
                                    ssp(t3.x + bj), ssp(t3.y + bj));
            *(float4*)&hT[(f0 + j) * RP + e0]     = v0;
            *(float4*)&hT[(f0 + j) * RP + e0 + 4] = v1;
        }
        __syncthreads();   // layer 2 reads ALL hT rows -> full barrier required

        // --- layer 2: K = 128, w2 from smem [k][f] ---
        u64 acc2[4][4];
#pragma unroll
        for (int p = 0; p < 4; p++)
#pragma unroll
            for (int j = 0; j < 4; j++) acc2[p][j] = 0ULL;

#pragma unroll 2
        for (int k = 0; k < NF; k++) {
            const float4 w4 = *(const float4*)&w2T[k * NF + f0];  // lane-spread, conflict-free
            u64 ws0 = splat2(w4.x), ws1 = splat2(w4.y);
            u64 ws2 = splat2(w4.z), ws3 = splat2(w4.w);
            const ulonglong2 a01 = *(const ulonglong2*)&hT[k * RP + e0];      // broadcast
            const ulonglong2 a23 = *(const ulonglong2*)&hT[k * RP + e0 + 4];  // broadcast
            u64 ap0 = a01.x, ap1 = a01.y, ap2 = a23.x, ap3 = a23.y;
            fma2(acc2[0][0], ap0, ws0); fma2(acc2[0][1], ap0, ws1);
            fma2(acc2[0][2], ap0, ws2); fma2(acc2[0][3], ap0, ws3);
            fma2(acc2[1][0], ap1, ws0); fma2(acc2[1][1], ap1, ws1);
            fma2(acc2[1][2], ap1, ws2); fma2(acc2[1][3], ap1, ws3);
            fma2(acc2[2][0], ap2, ws0); fma2(acc2[2][1], ap2, ws1);
            fma2(acc2[2][2], ap2, ws2); fma2(acc2[2][3], ap2, ws3);
            fma2(acc2[3][0], ap3, ws0); fma2(acc2[3][1], ap3, ws1);
            fma2(acc2[3][2], ap3, ws2); fma2(acc2[3][3], ap3, ws3);
        }

        // --- epilogue: W=(l2+b2)*C, msg = h[src]*W, vector atomic scatter ---
#pragma unroll
        for (int p = 0; p < 4; p++) {
            float2 t0 = unpack2(acc2[p][0]);   // .x = edge e0+2p, .y = edge e0+2p+1
            float2 t1 = unpack2(acc2[p][1]);
            float2 t2 = unpack2(acc2[p][2]);
            float2 t3 = unpack2(acc2[p][3]);
            int ia = e0 + 2 * p, ib = ia + 1;       // tile-local (smem arrays)
            int la = 2 * p,      lb = la + 1;       // hs[] local index (FIX)
            if (ebase + ia < E) {
                float ca = sC[ia];
                float4 ma = make_float4((t0.x + b2v.x) * ca * hs[la].x,
                                        (t1.x + b2v.y) * ca * hs[la].y,
                                        (t2.x + b2v.z) * ca * hs[la].z,
                                        (t3.x + b2v.w) * ca * hs[la].w);
                atomicAdd((float4*)(agg + (size_t)sDst[ia] * NF + f0), ma);
            }
            if (ebase + ib < E) {
                float cb = sC[ib];
                float4 mb = make_float4((t0.y + b2v.x) * cb * hs[lb].x,
                                        (t1.y + b2v.y) * cb * hs[lb].y,
                                        (t2.y + b2v.z) * cb * hs[lb].z,
                                        (t3.y + b2v.w) * cb * hs[lb].w);
                atomicAdd((float4*)(agg + (size_t)sDst[ib] * NF + f0), mb);
            }
        }
    }
}

// ---------------------------------------------------------------------------
// launch
// ---------------------------------------------------------------------------
extern "C" void kernel_launch(void* const* d_in, const int* in_sizes, int n_in,
                              void* d_out, int out_size)
{
    const float* x      = (const float*)d_in[0];
    const void*  ei     = d_in[1];
    const float* ew     = (const float*)d_in[2];
    const float* ea     = (const float*)d_in[3];
    const float* mlp_w1 = (const float*)d_in[4];
    const float* mlp_b1 = (const float*)d_in[5];
    const float* mlp_w2 = (const float*)d_in[6];
    const float* mlp_b2 = (const float*)d_in[7];
    const float* lin1_w = (const float*)d_in[8];
    const float* lin2_w = (const float*)d_in[9];
    const float* lin2_b = (const float*)d_in[10];
    const float* lin_w  = (const float*)d_in[11];
    const float* lin_b  = (const float*)d_in[12];

    const int N = in_sizes[0] / HID;
    const int E = in_sizes[1] / 2;

    float *hbuf, *aggbuf, *tmpbuf;
    cudaGetSymbolAddress((void**)&hbuf,   g_h);
    cudaGetSymbolAddress((void**)&aggbuf, g_agg);
    cudaGetSymbolAddress((void**)&tmpbuf, g_tmp);

    const int NODE_SMEM = (NF * NF + TE * NF) * 4;   // 98304 B
    cudaFuncSetAttribute(edge_kernel, cudaFuncAttributeMaxDynamicSharedMemorySize, EDGE_SMEM_BYTES);
    cudaFuncSetAttribute(node_gemm<false, false>, cudaFuncAttributeMaxDynamicSharedMemorySize, NODE_SMEM);
    cudaFuncSetAttribute(node_gemm<true,  true >, cudaFuncAttributeMaxDynamicSharedMemorySize, NODE_SMEM);
    cudaFuncSetAttribute(node_gemm<false, true >, cudaFuncAttributeMaxDynamicSharedMemorySize, NODE_SMEM);

    int dev = 0;
    cudaGetDevice(&dev);
    int sms = 148;
    cudaDeviceGetAttribute(&sms, cudaDevAttrMultiProcessorCount, dev);

    // 0. prep
    detect_idx_kernel<<<1, 256>>>((const unsigned int*)ei, 2 * E);
    convert_idx_kernel<<<(2 * E + 255) / 256, 256>>>(ei, 2 * E);
    transpose_w1_kernel<<<(NF * NG + 255) / 256, 256>>>(mlp_w1);
    {
        int n4 = (N * NF) / 4;
        zero_kernel<<<(n4 + 255) / 256, 256>>>((float4*)aggbuf, n4);
    }
    // 1. h = x @ lin1^T
    node_gemm<false, false><<<(N + TE - 1) / TE, 256, NODE_SMEM>>>(x, lin1_w, nullptr, hbuf, N);
    // 2. fused edge MLP + gather + scatter (persistent, 2 blocks/SM)
    edge_kernel<<<2 * sms, 256, EDGE_SMEM_BYTES>>>(ea, ew, mlp_b1,
                                                   mlp_w2, mlp_b2, hbuf, aggbuf, E);
    // 3. tmp = ssp(agg @ lin2^T + b2)
    node_gemm<true, true><<<(N + TE - 1) / TE, 256, NODE_SMEM>>>(aggbuf, lin2_w, lin2_b, tmpbuf, N);
    // 4. out = tmp @ lin^T + b
    node_gemm<false, true><<<(N + TE - 1) / TE, 256, NODE_SMEM>>>(tmpbuf, lin_w, lin_b, (float*)d_out, N);
}